// round 4
// baseline (speedup 1.0000x reference)
#include <cuda_runtime.h>
#include <cuda_bf16.h>
#include <cooperative_groups.h>
#include <cstdint>
#include <cstddef>

namespace cg = cooperative_groups;

// Problem dims
#define Vv 32000
#define Ee 300
#define Hh 300
#define G4 1200   // 4*H
#define Bb 128
#define Tt 512
#define Oo 9

// ---------------- scratch (device globals: allocation-free rule) ----------------
__device__ float g_proj[2ull * Vv * G4];          // 307.2 MB
__device__ float g_h[2ull * Bb * Tt * Hh];        // 157.3 MB

// ---------------- packed fp32x2 helpers (sm_100+ FFMA2) ----------------
typedef unsigned long long ull_t;

__device__ __forceinline__ void ffma2(ull_t& d, ull_t a, ull_t b) {
    asm("fma.rn.f32x2 %0, %1, %2, %0;" : "+l"(d) : "l"(a), "l"(b));
}
__device__ __forceinline__ ull_t pack_dup(float s) {
    ull_t d;
    asm("mov.b64 %0, {%1, %1};" : "=l"(d) : "r"(__float_as_uint(s)));
    return d;
}
union F4U { float4 f; ull_t u[2]; };
union U2F { ull_t u; float2 f; };

// =================================================================
// K1: vocab projection GEMM  C[v][n] = sum_k emb[v][k] * W[n][k] + bias[n]
// M = 32000, N = 1200, K = 300.  BM=128, BN=64, BK=16, 256 thr, 8x4 micro.
// Micro-kernel uses FFMA2 paired across M (As is m-contiguous).
// =================================================================
#define K1_BM 128
#define K1_BN 64
#define K1_BK 16

__global__ void proj_kernel(const float* __restrict__ emb,
                            const float* __restrict__ Wf,
                            const float* __restrict__ Wb,
                            const float* __restrict__ bf,
                            const float* __restrict__ bb) {
    __shared__ float As[K1_BK][K1_BM + 4];
    __shared__ float Bs[K1_BK][K1_BN + 4];

    const int dir = blockIdx.z;
    const float* __restrict__ W    = dir ? Wb : Wf;
    const float* __restrict__ bias = dir ? bb : bf;
    const int n0 = blockIdx.x * K1_BN;
    const int m0 = blockIdx.y * K1_BM;
    const int tid = threadIdx.x;
    const int tx = tid & 15;       // N dim (16 * 4 = 64)
    const int ty = tid >> 4;       // M dim (16 * 8 = 128)

    // acc2[pi][j]: pi = m-pair (rows 2pi, 2pi+1), j = n
    ull_t acc2[4][4];
#pragma unroll
    for (int i = 0; i < 4; i++)
#pragma unroll
        for (int j = 0; j < 4; j++) acc2[i][j] = 0ull;

    for (int kk = 0; kk < Ee; kk += K1_BK) {
        // ---- load A tile (emb rows), 2 float4 per thread ----
#pragma unroll
        for (int it = 0; it < 2; it++) {
            int f = tid + it * 256;
            int row = f >> 2;
            int kq  = (f & 3) * 4;
            int k0  = kk + kq;
            const float* src = emb + (size_t)(m0 + row) * Ee;
            float4 v;
            if (k0 + 3 < Ee) {
                v = *(const float4*)(src + k0);
            } else {
                v.x = (k0 + 0 < Ee) ? src[k0 + 0] : 0.f;
                v.y = (k0 + 1 < Ee) ? src[k0 + 1] : 0.f;
                v.z = (k0 + 2 < Ee) ? src[k0 + 2] : 0.f;
                v.w = (k0 + 3 < Ee) ? src[k0 + 3] : 0.f;
            }
            As[kq + 0][row] = v.x; As[kq + 1][row] = v.y;
            As[kq + 2][row] = v.z; As[kq + 3][row] = v.w;
        }
        // ---- load B tile (W_ih rows), 1 float4 per thread ----
        {
            int f = tid;
            int row = f >> 2;
            int kq  = (f & 3) * 4;
            int k0  = kk + kq;
            int n   = n0 + row;
            float4 v = make_float4(0.f, 0.f, 0.f, 0.f);
            if (n < G4) {
                const float* src = W + (size_t)n * Ee;
                if (k0 + 3 < Ee) {
                    v = *(const float4*)(src + k0);
                } else {
                    v.x = (k0 + 0 < Ee) ? src[k0 + 0] : 0.f;
                    v.y = (k0 + 1 < Ee) ? src[k0 + 1] : 0.f;
                    v.z = (k0 + 2 < Ee) ? src[k0 + 2] : 0.f;
                    v.w = (k0 + 3 < Ee) ? src[k0 + 3] : 0.f;
                }
            }
            Bs[kq + 0][row] = v.x; Bs[kq + 1][row] = v.y;
            Bs[kq + 2][row] = v.z; Bs[kq + 3][row] = v.w;
        }
        __syncthreads();

#pragma unroll
        for (int k = 0; k < K1_BK; k++) {
            F4U a0, a1, bv;
            a0.f = *(float4*)&As[k][ty * 8];
            a1.f = *(float4*)&As[k][ty * 8 + 4];
            bv.f = *(float4*)&Bs[k][tx * 4];
            ull_t ap[4] = {a0.u[0], a0.u[1], a1.u[0], a1.u[1]};
            ull_t bp[4] = {pack_dup(bv.f.x), pack_dup(bv.f.y),
                           pack_dup(bv.f.z), pack_dup(bv.f.w)};
#pragma unroll
            for (int pi = 0; pi < 4; pi++)
#pragma unroll
                for (int j = 0; j < 4; j++) ffma2(acc2[pi][j], ap[pi], bp[j]);
        }
        __syncthreads();
    }

    // ---- store with bias ----
    float* cbase = g_proj + (size_t)dir * Vv * G4;
#pragma unroll
    for (int pi = 0; pi < 4; pi++) {
        int m = m0 + ty * 8 + pi * 2;
#pragma unroll
        for (int j = 0; j < 4; j++) {
            int n = n0 + tx * 4 + j;
            if (n < G4) {
                U2F v; v.u = acc2[pi][j];
                float bn = bias[n];
                cbase[(size_t)(m + 0) * G4 + n] = v.f.x + bn;
                cbase[(size_t)(m + 1) * G4 + n] = v.f.y + bn;
            }
        }
    }
}

// =================================================================
// K2: BiLSTM recurrence. Cluster of 8 CTAs = (dir, 16 batch rows).
// CTA rank r owns hidden slice [r*40, r*40+40)  (300 total, last CTA 20 valid).
// SMEM layouts (k-contiguous for FFMA2 k-pairing):
//   W_s[gate_row 0..159][k, stride 308]   (192.5 KB)
//   h_s[row 0..15][k, stride 320]         (20 KB)  -- full h replicated per CTA
// threads = 160: thread = (rowgroup rg 0..3 [4 batch rows], hidden j 0..39)
// =================================================================
#define REC_THREADS 160
#define WS_STRIDE 308              // words; 77 x 16B units (odd -> conflict-free LDS.128)
#define HS_STRIDE 320              // words; room for rank-7 pad writes (cols 300..319)
#define REC_SMEM (160 * WS_STRIDE * 4 + 16 * HS_STRIDE * 4)   // 217600 B

__device__ __forceinline__ float sigmoidf_(float x) {
    return 1.0f / (1.0f + __expf(-x));
}
__device__ __forceinline__ float tanhf_(float x) {
    float xx = fminf(fmaxf(x, -15.f), 15.f);
    float e = __expf(-2.0f * xx);
    return (1.0f - e) / (1.0f + e);
}

__global__ void __cluster_dims__(8, 1, 1)
lstm_rec_kernel(const int* __restrict__ x,
                const float* __restrict__ Whh_f,
                const float* __restrict__ Whh_b) {
    extern __shared__ float sm[];
    float* W_s = sm;                          // [gi][k] gi = g*40 + j
    float* h_s = sm + 160 * WS_STRIDE;        // [row][k]

    cg::cluster_group cluster = cg::this_cluster();

    const int bx   = blockIdx.x;
    const int cid  = bx >> 3;           // 0..15
    const int rank = bx & 7;            // 0..7
    const int dir  = cid >> 3;          // 0,1
    const int bg   = cid & 7;           // 0..7
    const int b0   = bg * 16;
    const int h0   = rank * 40;
    const int tid  = threadIdx.x;
    const int j    = tid % 40;
    const int rg   = tid / 40;          // 0..3
    const bool validh = (h0 + j) < Hh;
    const int hjc = validh ? (h0 + j) : (Hh - 1);

    const float* __restrict__ Whh = dir ? Whh_b : Whh_f;

    // ---- load weight slice into SMEM, k-contiguous rows ----
    {
        int gi = tid;                    // 0..159
        int g  = gi / 40;
        int jj = gi % 40;
        bool v = (h0 + jj) < Hh;
        const float* wrow = Whh + (size_t)(g * Hh + (v ? (h0 + jj) : 0)) * Hh;
        float* dst = W_s + gi * WS_STRIDE;
        for (int k4 = 0; k4 < Hh; k4 += 4) {
            float4 w = v ? *(const float4*)(wrow + k4) : make_float4(0.f, 0.f, 0.f, 0.f);
            *(float4*)(dst + k4) = w;
        }
    }
    // ---- zero h ----
    for (int i = tid; i < 16 * HS_STRIDE; i += REC_THREADS) h_s[i] = 0.f;
    __syncthreads();

    const int* xr0 = x + (size_t)(b0 + rg * 4 + 0) * Tt;
    const int* xr1 = x + (size_t)(b0 + rg * 4 + 1) * Tt;
    const int* xr2 = x + (size_t)(b0 + rg * 4 + 2) * Tt;
    const int* xr3 = x + (size_t)(b0 + rg * 4 + 3) * Tt;
    const float* ptab = g_proj + (size_t)dir * Vv * G4;

    float c0 = 0.f, c1 = 0.f, c2 = 0.f, c3 = 0.f;

    const float* wp0 = W_s + (0 * 40 + j) * WS_STRIDE;
    const float* wp1 = W_s + (1 * 40 + j) * WS_STRIDE;
    const float* wp2 = W_s + (2 * 40 + j) * WS_STRIDE;
    const float* wp3 = W_s + (3 * 40 + j) * WS_STRIDE;
    const float* hp  = h_s + (rg * 4) * HS_STRIDE;

    // push-phase mapping: thread tid covers float4 #tid of own 40x16 slice
    const int push_row = tid / 10;            // 0..15
    const int push_off = push_row * HS_STRIDE + h0 + (tid % 10) * 4;

    for (int ti = 0; ti < Tt; ti++) {
        const int tcur = dir ? (Tt - 1 - ti) : ti;

        // gather pre-projected inputs for this step (i,f,g,o for 4 rows)
        const float* p0 = ptab + (size_t)xr0[tcur] * G4 + hjc;
        const float* p1 = ptab + (size_t)xr1[tcur] * G4 + hjc;
        const float* p2 = ptab + (size_t)xr2[tcur] * G4 + hjc;
        const float* p3 = ptab + (size_t)xr3[tcur] * G4 + hjc;
        float xp[16];
#pragma unroll
        for (int g = 0; g < 4; g++) {
            xp[0 * 4 + g] = p0[g * Hh];
            xp[1 * 4 + g] = p1[g * Hh];
            xp[2 * 4 + g] = p2[g * Hh];
            xp[3 * 4 + g] = p3[g * Hh];
        }

        // ---- gate dots: acc2[r][g] (f32x2, paired over k) ----
        ull_t acc2[4][4];
#pragma unroll
        for (int r = 0; r < 4; r++)
#pragma unroll
            for (int g = 0; g < 4; g++) acc2[r][g] = 0ull;

#pragma unroll 5
        for (int k = 0; k < Hh; k += 4) {
            F4U hv[4], wv[4];
            hv[0].f = *(const float4*)(hp + 0 * HS_STRIDE + k);
            hv[1].f = *(const float4*)(hp + 1 * HS_STRIDE + k);
            hv[2].f = *(const float4*)(hp + 2 * HS_STRIDE + k);
            hv[3].f = *(const float4*)(hp + 3 * HS_STRIDE + k);
            wv[0].f = *(const float4*)(wp0 + k);
            wv[1].f = *(const float4*)(wp1 + k);
            wv[2].f = *(const float4*)(wp2 + k);
            wv[3].f = *(const float4*)(wp3 + k);
#pragma unroll
            for (int r = 0; r < 4; r++) {
#pragma unroll
                for (int g = 0; g < 4; g++) {
                    ffma2(acc2[r][g], hv[r].u[0], wv[g].u[0]);
                    ffma2(acc2[r][g], hv[r].u[1], wv[g].u[1]);
                }
            }
        }

        float acc[16];
#pragma unroll
        for (int r = 0; r < 4; r++)
#pragma unroll
            for (int g = 0; g < 4; g++) {
                U2F v; v.u = acc2[r][g];
                acc[r * 4 + g] = v.f.x + v.f.y;
            }

        // ---- LSTM cell update (c in registers) ----
        float hn[4];
        {
            float gi_, gf_, gg_, go_, tg;
            gi_ = acc[0] + xp[0];  gf_ = acc[1] + xp[1];  gg_ = acc[2] + xp[2];  go_ = acc[3] + xp[3];
            tg = tanhf_(gg_); c0 = sigmoidf_(gf_) * c0 + sigmoidf_(gi_) * tg; hn[0] = sigmoidf_(go_) * tanhf_(c0);
            gi_ = acc[4] + xp[4];  gf_ = acc[5] + xp[5];  gg_ = acc[6] + xp[6];  go_ = acc[7] + xp[7];
            tg = tanhf_(gg_); c1 = sigmoidf_(gf_) * c1 + sigmoidf_(gi_) * tg; hn[1] = sigmoidf_(go_) * tanhf_(c1);
            gi_ = acc[8] + xp[8];  gf_ = acc[9] + xp[9];  gg_ = acc[10] + xp[10]; go_ = acc[11] + xp[11];
            tg = tanhf_(gg_); c2 = sigmoidf_(gf_) * c2 + sigmoidf_(gi_) * tg; hn[2] = sigmoidf_(go_) * tanhf_(c2);
            gi_ = acc[12] + xp[12]; gf_ = acc[13] + xp[13]; gg_ = acc[14] + xp[14]; go_ = acc[15] + xp[15];
            tg = tanhf_(gg_); c3 = sigmoidf_(gf_) * c3 + sigmoidf_(gi_) * tg; hn[3] = sigmoidf_(go_) * tanhf_(c3);
        }

        // ---- write h to global for the output stage (independent of h_s) ----
        if (validh) {
            size_t base = ((size_t)(dir * Bb + b0 + rg * 4) * Tt + tcur) * Hh + (h0 + j);
            const size_t strideB = (size_t)Tt * Hh;
            g_h[base + 0 * strideB] = hn[0];
            g_h[base + 1 * strideB] = hn[1];
            g_h[base + 2 * strideB] = hn[2];
            g_h[base + 3 * strideB] = hn[3];
        }

        cluster.sync();   // everyone finished reading h_s of step t-1

        // ---- stage new h locally (scattered scalars into own slice) ----
        {
            unsigned base = (unsigned)(rg * 4) * HS_STRIDE + (unsigned)(h0 + j);
            h_s[base + 0 * HS_STRIDE] = hn[0];
            h_s[base + 1 * HS_STRIDE] = hn[1];
            h_s[base + 2 * HS_STRIDE] = hn[2];
            h_s[base + 3 * HS_STRIDE] = hn[3];
        }
        __syncthreads();

        // ---- push own slice to 7 peers as float4 (DSMEM) ----
        {
            float4 v = *(const float4*)(h_s + push_off);
#pragma unroll
            for (int rr = 0; rr < 8; rr++) {
                if (rr == rank) continue;
                float* ph = cluster.map_shared_rank(h_s, rr);
                *(float4*)(ph + push_off) = v;
            }
        }

        cluster.sync();   // h_s complete for step t
    }
}

// =================================================================
// K3: output linear + softmax. One warp per (b,t).
// =================================================================
__global__ void out_kernel(const float* __restrict__ W_lin,
                           const float* __restrict__ b_lin,
                           float* __restrict__ out) {
    const int warp = (blockIdx.x * blockDim.x + threadIdx.x) >> 5;
    const int lane = threadIdx.x & 31;
    if (warp >= Bb * Tt) return;
    const int b = warp / Tt;
    const int t = warp % Tt;

    const float* hf = g_h + ((size_t)(0 * Bb + b) * Tt + t) * Hh;
    const float* hb = g_h + ((size_t)(1 * Bb + b) * Tt + t) * Hh;

    float acc[Oo];
#pragma unroll
    for (int o = 0; o < Oo; o++) acc[o] = 0.f;

    for (int k = lane; k < Hh; k += 32) {
        float a = hf[k];
        float c = hb[k];
#pragma unroll
        for (int o = 0; o < Oo; o++)
            acc[o] += a * W_lin[o * (2 * Hh) + k] + c * W_lin[o * (2 * Hh) + Hh + k];
    }
#pragma unroll
    for (int o = 0; o < Oo; o++) {
#pragma unroll
        for (int off = 16; off > 0; off >>= 1)
            acc[o] += __shfl_xor_sync(0xFFFFFFFFu, acc[o], off);
        acc[o] += b_lin[o];
    }
    // softmax over 9 (all lanes have identical values)
    float mx = acc[0];
#pragma unroll
    for (int o = 1; o < Oo; o++) mx = fmaxf(mx, acc[o]);
    float s = 0.f;
    float e[Oo];
#pragma unroll
    for (int o = 0; o < Oo; o++) { e[o] = __expf(acc[o] - mx); s += e[o]; }
    float inv = 1.0f / s;
    if (lane < Oo) out[(size_t)warp * Oo + lane] = e[lane] * inv;
}

// =================================================================
// launcher
// =================================================================
extern "C" void kernel_launch(void* const* d_in, const int* in_sizes, int n_in,
                              void* d_out, int out_size) {
    const int*   x     = (const int*)  d_in[0];
    const float* emb   = (const float*)d_in[1];
    const float* Wih_f = (const float*)d_in[2];
    const float* Whh_f = (const float*)d_in[3];
    const float* b_f   = (const float*)d_in[4];
    const float* Wih_b = (const float*)d_in[5];
    const float* Whh_b = (const float*)d_in[6];
    const float* b_b   = (const float*)d_in[7];
    const float* W_lin = (const float*)d_in[8];
    const float* b_lin = (const float*)d_in[9];
    float* out = (float*)d_out;

    cudaFuncSetAttribute(lstm_rec_kernel,
                         cudaFuncAttributeMaxDynamicSharedMemorySize, REC_SMEM);

    // K1: vocab projection. grid = (N tiles, M tiles, dir)
    {
        dim3 grid((G4 + K1_BN - 1) / K1_BN, Vv / K1_BM, 2);
        proj_kernel<<<grid, 256>>>(emb, Wih_f, Wih_b, b_f, b_b);
    }
    // K2: recurrence. 128 CTAs, clusters of 8.
    lstm_rec_kernel<<<128, REC_THREADS, REC_SMEM>>>(x, Whh_f, Whh_b);

    // K3: output. 65536 warps.
    {
        int warps_per_block = 8;
        int blocks = (Bb * Tt) / warps_per_block;
        out_kernel<<<blocks, warps_per_block * 32>>>(W_lin, b_lin, out);
    }
}

// round 6
// speedup vs baseline: 1.5232x; 1.5232x over previous
#include <cuda_runtime.h>
#include <cuda_bf16.h>
#include <cooperative_groups.h>
#include <cstdint>
#include <cstddef>

namespace cg = cooperative_groups;

// Problem dims
#define Vv 32000
#define Ee 300
#define Hh 300
#define G4 1200   // 4*H
#define Bb 128
#define Tt 512
#define Oo 9

// ---------------- scratch (device globals: allocation-free rule) ----------------
__device__ float g_proj[2ull * Vv * G4];          // 307.2 MB
__device__ float g_h[2ull * Bb * Tt * Hh];        // 157.3 MB

// ---------------- packed fp32x2 helpers (sm_100+ FFMA2) ----------------
typedef unsigned long long ull_t;

__device__ __forceinline__ void ffma2(ull_t& d, ull_t a, ull_t b) {
    asm("fma.rn.f32x2 %0, %1, %2, %0;" : "+l"(d) : "l"(a), "l"(b));
}
union F4U { float4 f; ull_t u[2]; };
union U2F { ull_t u; float2 f; };

// =================================================================
// K1: vocab projection GEMM  C[v][n] = sum_k emb[v][k] * W[n][k] + bias[n]
// M = 32000, N = 1200, K = 300.  BM=128, BN=64, BK=16, 256 thr, 8x4 micro.
// (exact R2 version — known-good: occ 49%, fma 54%)
// =================================================================
#define K1_BM 128
#define K1_BN 64
#define K1_BK 16

__global__ void proj_kernel(const float* __restrict__ emb,
                            const float* __restrict__ Wf,
                            const float* __restrict__ Wb,
                            const float* __restrict__ bf,
                            const float* __restrict__ bb) {
    __shared__ float As[K1_BK][K1_BM + 4];
    __shared__ float Bs[K1_BK][K1_BN + 4];

    const int dir = blockIdx.z;
    const float* __restrict__ W    = dir ? Wb : Wf;
    const float* __restrict__ bias = dir ? bb : bf;
    const int n0 = blockIdx.x * K1_BN;
    const int m0 = blockIdx.y * K1_BM;
    const int tid = threadIdx.x;
    const int tx = tid & 15;       // N dim (16 * 4 = 64)
    const int ty = tid >> 4;       // M dim (16 * 8 = 128)

    float acc[8][4];
#pragma unroll
    for (int i = 0; i < 8; i++)
#pragma unroll
        for (int j = 0; j < 4; j++) acc[i][j] = 0.f;

    for (int kk = 0; kk < Ee; kk += K1_BK) {
        // ---- load A tile (emb rows), 2 float4 per thread ----
#pragma unroll
        for (int it = 0; it < 2; it++) {
            int f = tid + it * 256;
            int row = f >> 2;
            int kq  = (f & 3) * 4;
            int k0  = kk + kq;
            const float* src = emb + (size_t)(m0 + row) * Ee;
            float4 v;
            if (k0 + 3 < Ee) {
                v = *(const float4*)(src + k0);
            } else {
                v.x = (k0 + 0 < Ee) ? src[k0 + 0] : 0.f;
                v.y = (k0 + 1 < Ee) ? src[k0 + 1] : 0.f;
                v.z = (k0 + 2 < Ee) ? src[k0 + 2] : 0.f;
                v.w = (k0 + 3 < Ee) ? src[k0 + 3] : 0.f;
            }
            As[kq + 0][row] = v.x; As[kq + 1][row] = v.y;
            As[kq + 2][row] = v.z; As[kq + 3][row] = v.w;
        }
        // ---- load B tile (W_ih rows), 1 float4 per thread ----
        {
            int f = tid;
            int row = f >> 2;
            int kq  = (f & 3) * 4;
            int k0  = kk + kq;
            int n   = n0 + row;
            float4 v = make_float4(0.f, 0.f, 0.f, 0.f);
            if (n < G4) {
                const float* src = W + (size_t)n * Ee;
                if (k0 + 3 < Ee) {
                    v = *(const float4*)(src + k0);
                } else {
                    v.x = (k0 + 0 < Ee) ? src[k0 + 0] : 0.f;
                    v.y = (k0 + 1 < Ee) ? src[k0 + 1] : 0.f;
                    v.z = (k0 + 2 < Ee) ? src[k0 + 2] : 0.f;
                    v.w = (k0 + 3 < Ee) ? src[k0 + 3] : 0.f;
                }
            }
            Bs[kq + 0][row] = v.x; Bs[kq + 1][row] = v.y;
            Bs[kq + 2][row] = v.z; Bs[kq + 3][row] = v.w;
        }
        __syncthreads();

#pragma unroll
        for (int k = 0; k < K1_BK; k++) {
            float4 a0 = *(float4*)&As[k][ty * 8];
            float4 a1 = *(float4*)&As[k][ty * 8 + 4];
            float4 bv = *(float4*)&Bs[k][tx * 4];
            float av[8] = {a0.x, a0.y, a0.z, a0.w, a1.x, a1.y, a1.z, a1.w};
            float bvv[4] = {bv.x, bv.y, bv.z, bv.w};
#pragma unroll
            for (int i = 0; i < 8; i++)
#pragma unroll
                for (int j = 0; j < 4; j++) acc[i][j] += av[i] * bvv[j];
        }
        __syncthreads();
    }

    // ---- store with bias ----
    float* cbase = g_proj + (size_t)dir * Vv * G4;
#pragma unroll
    for (int i = 0; i < 8; i++) {
        int m = m0 + ty * 8 + i;
#pragma unroll
        for (int j = 0; j < 4; j++) {
            int n = n0 + tx * 4 + j;
            if (n < G4) cbase[(size_t)m * G4 + n] = acc[i][j] + bias[n];
        }
    }
}

// =================================================================
// K2: BiLSTM recurrence. Cluster of 8 CTAs = (dir, 16 batch rows).
// CTA rank r owns hidden slice [r*40, r*40+40)  (300 total, last CTA 20 valid).
// k-pair-interleaved SMEM layouts (FFMA2, conflict-free):
//   W_s2[k2 0..149][gi 0..159][2]   word off = k2*320 + gi*2 + p   (192.0 KB)
//   h_s2[k2 0..159][r 0..15][2]     word off = k2*32  + r*2  + p   ( 20.5 KB)
// threads = 160: thread = (rowgroup rg 0..3 [4 batch rows], hidden j 0..39)
// =================================================================
#define REC_THREADS 160
#define W2_WORDS (150 * 320)               // 48000
#define H2_WORDS (160 * 32)                // 5120 (k2 150..159 = pad for rank 7)
#define REC_SMEM ((W2_WORDS + H2_WORDS) * 4)   // 212480 B

__device__ __forceinline__ float sigmoidf_(float x) {
    return 1.0f / (1.0f + __expf(-x));
}
__device__ __forceinline__ float tanhf_(float x) {
    float xx = fminf(fmaxf(x, -15.f), 15.f);
    float e = __expf(-2.0f * xx);
    return (1.0f - e) / (1.0f + e);
}

__global__ void __cluster_dims__(8, 1, 1)
lstm_rec_kernel(const int* __restrict__ x,
                const float* __restrict__ Whh_f,
                const float* __restrict__ Whh_b) {
    extern __shared__ float sm[];
    float* W_s2 = sm;                 // [k2][gi][2]
    float* h_s2 = sm + W2_WORDS;      // [k2][r][2]

    cg::cluster_group cluster = cg::this_cluster();

    const int bx   = blockIdx.x;
    const int cid  = bx >> 3;           // 0..15
    const int rank = bx & 7;            // 0..7
    const int dir  = cid >> 3;          // 0,1
    const int bg   = cid & 7;           // 0..7
    const int b0   = bg * 16;
    const int h0   = rank * 40;
    const int tid  = threadIdx.x;
    const int j    = tid % 40;
    const int rg   = tid / 40;          // 0..3
    const bool validh = (h0 + j) < Hh;
    const int hjc = validh ? (h0 + j) : (Hh - 1);

    const float* __restrict__ Whh = dir ? Whh_b : Whh_f;

    // ---- load weight slice into SMEM, k-pair interleaved ----
    {
        int gi = tid;                    // 0..159
        int g  = gi / 40;
        int jj = gi % 40;
        bool v = (h0 + jj) < Hh;
        const float* wrow = Whh + (size_t)(g * Hh + (v ? (h0 + jj) : 0)) * Hh;
        for (int k4 = 0; k4 < Hh; k4 += 4) {
            float4 w = v ? *(const float4*)(wrow + k4) : make_float4(0.f, 0.f, 0.f, 0.f);
            int k2 = k4 >> 1;
            *(float2*)(W_s2 + (k2 + 0) * 320 + gi * 2) = make_float2(w.x, w.y);
            *(float2*)(W_s2 + (k2 + 1) * 320 + gi * 2) = make_float2(w.z, w.w);
        }
    }
    // ---- zero h ----
    for (int i = tid; i < H2_WORDS; i += REC_THREADS) h_s2[i] = 0.f;
    __syncthreads();

    const int* xr0 = x + (size_t)(b0 + rg * 4 + 0) * Tt;
    const int* xr1 = x + (size_t)(b0 + rg * 4 + 1) * Tt;
    const int* xr2 = x + (size_t)(b0 + rg * 4 + 2) * Tt;
    const int* xr3 = x + (size_t)(b0 + rg * 4 + 3) * Tt;
    const float* ptab = g_proj + (size_t)dir * Vv * G4;

    float c0 = 0.f, c1 = 0.f, c2 = 0.f, c3 = 0.f;

    // per-thread SMEM bases for the gate loop
    const float* wb0 = W_s2 + (0 * 40 + j) * 2;
    const float* wb1 = W_s2 + (1 * 40 + j) * 2;
    const float* wb2 = W_s2 + (2 * 40 + j) * 2;
    const float* wb3 = W_s2 + (3 * 40 + j) * 2;
    const float* hb  = h_s2 + (rg * 4) * 2;

    // staging offsets for own h values (scalar, conflict-free: consecutive j -> consecutive words)
    const unsigned stage_base = ((unsigned)(h0 + j) >> 1) * 32 + ((unsigned)(h0 + j) & 1);
    // push mapping: own slice = contiguous words [h0*16, h0*16 + 640); thread covers float4 #tid
    const unsigned push_off = (unsigned)(h0 * 16) + (unsigned)tid * 4;

    // ---- prologue: gather xp for step 0 ----
    float xp[16];
    {
        const int t0 = dir ? (Tt - 1) : 0;
        const float* p0 = ptab + (size_t)xr0[t0] * G4 + hjc;
        const float* p1 = ptab + (size_t)xr1[t0] * G4 + hjc;
        const float* p2 = ptab + (size_t)xr2[t0] * G4 + hjc;
        const float* p3 = ptab + (size_t)xr3[t0] * G4 + hjc;
#pragma unroll
        for (int g = 0; g < 4; g++) {
            xp[0 * 4 + g] = p0[g * Hh];
            xp[1 * 4 + g] = p1[g * Hh];
            xp[2 * 4 + g] = p2[g * Hh];
            xp[3 * 4 + g] = p3[g * Hh];
        }
    }

    for (int ti = 0; ti < Tt; ti++) {
        const int tcur = dir ? (Tt - 1 - ti) : ti;

        // ---- prefetch next step's xp (hidden behind the gate loop) ----
        float xpn[16];
        {
            const int tin = (ti + 1 < Tt) ? (ti + 1) : ti;
            const int tn  = dir ? (Tt - 1 - tin) : tin;
            const float* p0 = ptab + (size_t)xr0[tn] * G4 + hjc;
            const float* p1 = ptab + (size_t)xr1[tn] * G4 + hjc;
            const float* p2 = ptab + (size_t)xr2[tn] * G4 + hjc;
            const float* p3 = ptab + (size_t)xr3[tn] * G4 + hjc;
#pragma unroll
            for (int g = 0; g < 4; g++) {
                xpn[0 * 4 + g] = p0[g * Hh];
                xpn[1 * 4 + g] = p1[g * Hh];
                xpn[2 * 4 + g] = p2[g * Hh];
                xpn[3 * 4 + g] = p3[g * Hh];
            }
        }

        // ---- gate dots: acc2[r][g], f32x2 paired over (k even, k odd) ----
        ull_t acc2[4][4];
#pragma unroll
        for (int r = 0; r < 4; r++)
#pragma unroll
            for (int g = 0; g < 4; g++) acc2[r][g] = 0ull;

#pragma unroll 5
        for (int k2 = 0; k2 < 150; k2++) {
            // w pairs for the 4 gates (LDS.64, 8B stride across lanes: conflict-free)
            ull_t wv0 = *(const ull_t*)(wb0 + k2 * 320);
            ull_t wv1 = *(const ull_t*)(wb1 + k2 * 320);
            ull_t wv2 = *(const ull_t*)(wb2 + k2 * 320);
            ull_t wv3 = *(const ull_t*)(wb3 + k2 * 320);
            // h pairs for 4 rows (2x LDS.128, broadcast within rowgroup)
            F4U h01, h23;
            h01.f = *(const float4*)(hb + k2 * 32);
            h23.f = *(const float4*)(hb + k2 * 32 + 4);
            ffma2(acc2[0][0], h01.u[0], wv0); ffma2(acc2[0][1], h01.u[0], wv1);
            ffma2(acc2[0][2], h01.u[0], wv2); ffma2(acc2[0][3], h01.u[0], wv3);
            ffma2(acc2[1][0], h01.u[1], wv0); ffma2(acc2[1][1], h01.u[1], wv1);
            ffma2(acc2[1][2], h01.u[1], wv2); ffma2(acc2[1][3], h01.u[1], wv3);
            ffma2(acc2[2][0], h23.u[0], wv0); ffma2(acc2[2][1], h23.u[0], wv1);
            ffma2(acc2[2][2], h23.u[0], wv2); ffma2(acc2[2][3], h23.u[0], wv3);
            ffma2(acc2[3][0], h23.u[1], wv0); ffma2(acc2[3][1], h23.u[1], wv1);
            ffma2(acc2[3][2], h23.u[1], wv2); ffma2(acc2[3][3], h23.u[1], wv3);
        }

        float acc[16];
#pragma unroll
        for (int r = 0; r < 4; r++)
#pragma unroll
            for (int g = 0; g < 4; g++) {
                U2F v; v.u = acc2[r][g];
                acc[r * 4 + g] = v.f.x + v.f.y;
            }

        // ---- LSTM cell update (c in registers) ----
        float hn[4];
        {
            float gi_, gf_, gg_, go_, tg;
            gi_ = acc[0] + xp[0];  gf_ = acc[1] + xp[1];  gg_ = acc[2] + xp[2];  go_ = acc[3] + xp[3];
            tg = tanhf_(gg_); c0 = sigmoidf_(gf_) * c0 + sigmoidf_(gi_) * tg; hn[0] = sigmoidf_(go_) * tanhf_(c0);
            gi_ = acc[4] + xp[4];  gf_ = acc[5] + xp[5];  gg_ = acc[6] + xp[6];  go_ = acc[7] + xp[7];
            tg = tanhf_(gg_); c1 = sigmoidf_(gf_) * c1 + sigmoidf_(gi_) * tg; hn[1] = sigmoidf_(go_) * tanhf_(c1);
            gi_ = acc[8] + xp[8];  gf_ = acc[9] + xp[9];  gg_ = acc[10] + xp[10]; go_ = acc[11] + xp[11];
            tg = tanhf_(gg_); c2 = sigmoidf_(gf_) * c2 + sigmoidf_(gi_) * tg; hn[2] = sigmoidf_(go_) * tanhf_(c2);
            gi_ = acc[12] + xp[12]; gf_ = acc[13] + xp[13]; gg_ = acc[14] + xp[14]; go_ = acc[15] + xp[15];
            tg = tanhf_(gg_); c3 = sigmoidf_(gf_) * c3 + sigmoidf_(gi_) * tg; hn[3] = sigmoidf_(go_) * tanhf_(c3);
        }

        // ---- write h to global for the output stage (independent of h_s2) ----
        if (validh) {
            size_t base = ((size_t)(dir * Bb + b0 + rg * 4) * Tt + tcur) * Hh + (h0 + j);
            const size_t strideB = (size_t)Tt * Hh;
            g_h[base + 0 * strideB] = hn[0];
            g_h[base + 1 * strideB] = hn[1];
            g_h[base + 2 * strideB] = hn[2];
            g_h[base + 3 * strideB] = hn[3];
        }

        cluster.sync();   // all ranks finished reading h_s2 of step t-1

        // ---- stage new h locally (scalar, conflict-free) ----
        h_s2[stage_base + (rg * 4 + 0) * 2] = hn[0];
        h_s2[stage_base + (rg * 4 + 1) * 2] = hn[1];
        h_s2[stage_base + (rg * 4 + 2) * 2] = hn[2];
        h_s2[stage_base + (rg * 4 + 3) * 2] = hn[3];
        __syncthreads();

        // ---- push own contiguous slice (2.5 KB) to 7 peers as float4 ----
        {
            float4 v = *(const float4*)(h_s2 + push_off);
#pragma unroll
            for (int rr = 0; rr < 8; rr++) {
                if (rr == rank) continue;
                float* ph = cluster.map_shared_rank(h_s2, rr);
                *(float4*)(ph + push_off) = v;
            }
        }

        cluster.sync();   // h_s2 complete for step t

        xp[0]=xpn[0]; xp[1]=xpn[1]; xp[2]=xpn[2]; xp[3]=xpn[3];
        xp[4]=xpn[4]; xp[5]=xpn[5]; xp[6]=xpn[6]; xp[7]=xpn[7];
        xp[8]=xpn[8]; xp[9]=xpn[9]; xp[10]=xpn[10]; xp[11]=xpn[11];
        xp[12]=xpn[12]; xp[13]=xpn[13]; xp[14]=xpn[14]; xp[15]=xpn[15];
    }
}

// =================================================================
// K3: output linear + softmax. One warp per (b,t).
// =================================================================
__global__ void out_kernel(const float* __restrict__ W_lin,
                           const float* __restrict__ b_lin,
                           float* __restrict__ out) {
    const int warp = (blockIdx.x * blockDim.x + threadIdx.x) >> 5;
    const int lane = threadIdx.x & 31;
    if (warp >= Bb * Tt) return;
    const int b = warp / Tt;
    const int t = warp % Tt;

    const float* hf = g_h + ((size_t)(0 * Bb + b) * Tt + t) * Hh;
    const float* hb = g_h + ((size_t)(1 * Bb + b) * Tt + t) * Hh;

    float acc[Oo];
#pragma unroll
    for (int o = 0; o < Oo; o++) acc[o] = 0.f;

    for (int k = lane; k < Hh; k += 32) {
        float a = hf[k];
        float c = hb[k];
#pragma unroll
        for (int o = 0; o < Oo; o++)
            acc[o] += a * W_lin[o * (2 * Hh) + k] + c * W_lin[o * (2 * Hh) + Hh + k];
    }
#pragma unroll
    for (int o = 0; o < Oo; o++) {
#pragma unroll
        for (int off = 16; off > 0; off >>= 1)
            acc[o] += __shfl_xor_sync(0xFFFFFFFFu, acc[o], off);
        acc[o] += b_lin[o];
    }
    // softmax over 9 (all lanes have identical values)
    float mx = acc[0];
#pragma unroll
    for (int o = 1; o < Oo; o++) mx = fmaxf(mx, acc[o]);
    float s = 0.f;
    float e[Oo];
#pragma unroll
    for (int o = 0; o < Oo; o++) { e[o] = __expf(acc[o] - mx); s += e[o]; }
    float inv = 1.0f / s;
    if (lane < Oo) out[(size_t)warp * Oo + lane] = e[lane] * inv;
}

// =================================================================
// launcher
// =================================================================
extern "C" void kernel_launch(void* const* d_in, const int* in_sizes, int n_in,
                              void* d_out, int out_size) {
    const int*   x     = (const int*)  d_in[0];
    const float* emb   = (const float*)d_in[1];
    const float* Wih_f = (const float*)d_in[2];
    const float* Whh_f = (const float*)d_in[3];
    const float* b_f   = (const float*)d_in[4];
    const float* Wih_b = (const float*)d_in[5];
    const float* Whh_b = (const float*)d_in[6];
    const float* b_b   = (const float*)d_in[7];
    const float* W_lin = (const float*)d_in[8];
    const float* b_lin = (const float*)d_in[9];
    float* out = (float*)d_out;

    cudaFuncSetAttribute(lstm_rec_kernel,
                         cudaFuncAttributeMaxDynamicSharedMemorySize, REC_SMEM);

    // K1: vocab projection. grid = (N tiles, M tiles, dir)
    {
        dim3 grid((G4 + K1_BN - 1) / K1_BN, Vv / K1_BM, 2);
        proj_kernel<<<grid, 256>>>(emb, Wih_f, Wih_b, b_f, b_b);
    }
    // K2: recurrence. 128 CTAs, clusters of 8.
    lstm_rec_kernel<<<128, REC_THREADS, REC_SMEM>>>(x, Whh_f, Whh_b);

    // K3: output. 65536 warps.
    {
        int warps_per_block = 8;
        int blocks = (Bb * Tt) / warps_per_block;
        out_kernel<<<blocks, warps_per_block * 32>>>(W_lin, b_lin, out);
    }
}

// round 7
// speedup vs baseline: 1.5686x; 1.0298x over previous
#include <cuda_runtime.h>
#include <cuda_bf16.h>
#include <cooperative_groups.h>
#include <cstdint>
#include <cstddef>

namespace cg = cooperative_groups;

// Problem dims
#define Vv 32000
#define Ee 300
#define Hh 300
#define G4 1200   // 4*H
#define Bb 128
#define Tt 512
#define Oo 9

// ---------------- scratch (device globals: allocation-free rule) ----------------
__device__ float g_proj[2ull * Vv * G4];          // 307.2 MB
__device__ float g_h[2ull * Bb * Tt * Hh];        // 157.3 MB

// ---------------- packed fp32x2 helpers (sm_100+ FFMA2) ----------------
typedef unsigned long long ull_t;

__device__ __forceinline__ void ffma2(ull_t& d, ull_t a, ull_t b) {
    asm("fma.rn.f32x2 %0, %1, %2, %0;" : "+l"(d) : "l"(a), "l"(b));
}
union F4U { float4 f; ull_t u[2]; };
union U2F { ull_t u; float2 f; };

// ---------------- mbarrier helpers (cluster scope) ----------------
__device__ __forceinline__ void mbar_init(uint32_t addr, uint32_t count) {
    asm volatile("mbarrier.init.shared.b64 [%0], %1;" :: "r"(addr), "r"(count) : "memory");
}
__device__ __forceinline__ void mbar_arrive_rank(uint32_t local_mbar_addr, uint32_t rank) {
    asm volatile(
        "{\n\t"
        ".reg .b32 ra;\n\t"
        "mapa.shared::cluster.u32 ra, %0, %1;\n\t"
        "mbarrier.arrive.shared::cluster.b64 _, [ra];\n\t"
        "}"
        :: "r"(local_mbar_addr), "r"(rank) : "memory");
}
__device__ __forceinline__ void mbar_wait_parity_acq_cluster(uint32_t addr, uint32_t parity) {
    uint32_t done;
    asm volatile(
        "{\n\t"
        ".reg .pred p;\n\t"
        "mbarrier.try_wait.parity.acquire.cluster.shared::cta.b64 p, [%1], %2;\n\t"
        "selp.b32 %0, 1, 0, p;\n\t"
        "}"
        : "=r"(done) : "r"(addr), "r"(parity) : "memory");
    while (!done) {
        asm volatile(
            "{\n\t"
            ".reg .pred p;\n\t"
            "mbarrier.try_wait.parity.acquire.cluster.shared::cta.b64 p, [%1], %2, 0x989680;\n\t"
            "selp.b32 %0, 1, 0, p;\n\t"
            "}"
            : "=r"(done) : "r"(addr), "r"(parity) : "memory");
    }
}

// =================================================================
// K1: vocab projection GEMM  C[v][n] = sum_k emb[v][k] * W[n][k] + bias[n]
// M = 32000, N = 1200, K = 300.  BM=128, BN=64, BK=16, 256 thr, 8x4 micro.
// (known-good R2 version)
// =================================================================
#define K1_BM 128
#define K1_BN 64
#define K1_BK 16

__global__ void proj_kernel(const float* __restrict__ emb,
                            const float* __restrict__ Wf,
                            const float* __restrict__ Wb,
                            const float* __restrict__ bf,
                            const float* __restrict__ bb) {
    __shared__ float As[K1_BK][K1_BM + 4];
    __shared__ float Bs[K1_BK][K1_BN + 4];

    const int dir = blockIdx.z;
    const float* __restrict__ W    = dir ? Wb : Wf;
    const float* __restrict__ bias = dir ? bb : bf;
    const int n0 = blockIdx.x * K1_BN;
    const int m0 = blockIdx.y * K1_BM;
    const int tid = threadIdx.x;
    const int tx = tid & 15;       // N dim (16 * 4 = 64)
    const int ty = tid >> 4;       // M dim (16 * 8 = 128)

    float acc[8][4];
#pragma unroll
    for (int i = 0; i < 8; i++)
#pragma unroll
        for (int j = 0; j < 4; j++) acc[i][j] = 0.f;

    for (int kk = 0; kk < Ee; kk += K1_BK) {
#pragma unroll
        for (int it = 0; it < 2; it++) {
            int f = tid + it * 256;
            int row = f >> 2;
            int kq  = (f & 3) * 4;
            int k0  = kk + kq;
            const float* src = emb + (size_t)(m0 + row) * Ee;
            float4 v;
            if (k0 + 3 < Ee) {
                v = *(const float4*)(src + k0);
            } else {
                v.x = (k0 + 0 < Ee) ? src[k0 + 0] : 0.f;
                v.y = (k0 + 1 < Ee) ? src[k0 + 1] : 0.f;
                v.z = (k0 + 2 < Ee) ? src[k0 + 2] : 0.f;
                v.w = (k0 + 3 < Ee) ? src[k0 + 3] : 0.f;
            }
            As[kq + 0][row] = v.x; As[kq + 1][row] = v.y;
            As[kq + 2][row] = v.z; As[kq + 3][row] = v.w;
        }
        {
            int f = tid;
            int row = f >> 2;
            int kq  = (f & 3) * 4;
            int k0  = kk + kq;
            int n   = n0 + row;
            float4 v = make_float4(0.f, 0.f, 0.f, 0.f);
            if (n < G4) {
                const float* src = W + (size_t)n * Ee;
                if (k0 + 3 < Ee) {
                    v = *(const float4*)(src + k0);
                } else {
                    v.x = (k0 + 0 < Ee) ? src[k0 + 0] : 0.f;
                    v.y = (k0 + 1 < Ee) ? src[k0 + 1] : 0.f;
                    v.z = (k0 + 2 < Ee) ? src[k0 + 2] : 0.f;
                    v.w = (k0 + 3 < Ee) ? src[k0 + 3] : 0.f;
                }
            }
            Bs[kq + 0][row] = v.x; Bs[kq + 1][row] = v.y;
            Bs[kq + 2][row] = v.z; Bs[kq + 3][row] = v.w;
        }
        __syncthreads();

#pragma unroll
        for (int k = 0; k < K1_BK; k++) {
            float4 a0 = *(float4*)&As[k][ty * 8];
            float4 a1 = *(float4*)&As[k][ty * 8 + 4];
            float4 bv = *(float4*)&Bs[k][tx * 4];
            float av[8] = {a0.x, a0.y, a0.z, a0.w, a1.x, a1.y, a1.z, a1.w};
            float bvv[4] = {bv.x, bv.y, bv.z, bv.w};
#pragma unroll
            for (int i = 0; i < 8; i++)
#pragma unroll
                for (int j = 0; j < 4; j++) acc[i][j] += av[i] * bvv[j];
        }
        __syncthreads();
    }

    float* cbase = g_proj + (size_t)dir * Vv * G4;
#pragma unroll
    for (int i = 0; i < 8; i++) {
        int m = m0 + ty * 8 + i;
#pragma unroll
        for (int j = 0; j < 4; j++) {
            int n = n0 + tx * 4 + j;
            if (n < G4) cbase[(size_t)m * G4 + n] = acc[i][j] + bias[n];
        }
    }
}

// =================================================================
// K2: BiLSTM recurrence. Cluster of 8 CTAs = (dir, 16 batch rows).
// CTA rank r owns hidden slice [r*40, r*40+40)  (300 total, last CTA 20 valid).
// SMEM:
//   W_s2[k2 0..149][gi 0..159][2]       48000 words (192.0 KB)
//   hbuf[2][k2 0..149][r 0..15][2]      2 x 4800 words (2 x 19.2 KB)
// Double-buffered mbarrier pipeline: ONE acquire-wait per step, no
// cluster.sync (no CCTL.IVALL L1 flushes) inside the loop.
// threads = 160: thread = (rowgroup rg 0..3 [4 batch rows], hidden j 0..39)
// =================================================================
#define REC_THREADS 160
#define W2_WORDS (150 * 320)               // 48000
#define HB_WORDS (150 * 32)                // 4800 per buffer
#define REC_SMEM ((W2_WORDS + 2 * HB_WORDS) * 4)   // 230400 B

__device__ __forceinline__ float sigmoidf_(float x) {
    return 1.0f / (1.0f + __expf(-x));
}
__device__ __forceinline__ float tanhf_(float x) {
    float xx = fminf(fmaxf(x, -15.f), 15.f);
    float e = __expf(-2.0f * xx);
    return (1.0f - e) / (1.0f + e);
}

__global__ void __cluster_dims__(8, 1, 1)
lstm_rec_kernel(const int* __restrict__ x,
                const float* __restrict__ Whh_f,
                const float* __restrict__ Whh_b) {
    extern __shared__ float sm[];
    float* W_s2 = sm;                         // [k2][gi][2]
    float* hbuf0 = sm + W2_WORDS;             // [k2][r][2]
    float* hbuf1 = sm + W2_WORDS + HB_WORDS;  // [k2][r][2]
    __shared__ unsigned long long mbars[2];

    cg::cluster_group cluster = cg::this_cluster();

    const int bx   = blockIdx.x;
    const int cid  = bx >> 3;           // 0..15
    const int rank = bx & 7;            // 0..7
    const int dir  = cid >> 3;          // 0,1
    const int bg   = cid & 7;           // 0..7
    const int b0   = bg * 16;
    const int h0   = rank * 40;
    const int tid  = threadIdx.x;
    const int j    = tid % 40;
    const int rg   = tid / 40;          // 0..3
    const bool validh = (h0 + j) < Hh;
    const int hjc = validh ? (h0 + j) : (Hh - 1);

    const float* __restrict__ Whh = dir ? Whh_b : Whh_f;

    const uint32_t mbar_addr0 = (uint32_t)__cvta_generic_to_shared(&mbars[0]);
    const uint32_t mbar_addr1 = (uint32_t)__cvta_generic_to_shared(&mbars[1]);

    // ---- init barriers (count = 8: one aggregated arrive per CTA) ----
    if (tid == 0) {
        mbar_init(mbar_addr0, 8);
        mbar_init(mbar_addr1, 8);
    }

    // ---- load weight slice into SMEM, k-pair interleaved ----
    {
        int gi = tid;                    // 0..159
        int g  = gi / 40;
        int jj = gi % 40;
        bool v = (h0 + jj) < Hh;
        const float* wrow = Whh + (size_t)(g * Hh + (v ? (h0 + jj) : 0)) * Hh;
        for (int k4 = 0; k4 < Hh; k4 += 4) {
            float4 w = v ? *(const float4*)(wrow + k4) : make_float4(0.f, 0.f, 0.f, 0.f);
            int k2 = k4 >> 1;
            *(float2*)(W_s2 + (k2 + 0) * 320 + gi * 2) = make_float2(w.x, w.y);
            *(float2*)(W_s2 + (k2 + 1) * 320 + gi * 2) = make_float2(w.z, w.w);
        }
    }
    // ---- zero h buffers ----
    for (int i = tid; i < 2 * HB_WORDS; i += REC_THREADS) hbuf0[i] = 0.f;
    __syncthreads();
    // one-time: barriers + zeroed buffers visible cluster-wide before any push
    cluster.sync();

    const int* xr0 = x + (size_t)(b0 + rg * 4 + 0) * Tt;
    const int* xr1 = x + (size_t)(b0 + rg * 4 + 1) * Tt;
    const int* xr2 = x + (size_t)(b0 + rg * 4 + 2) * Tt;
    const int* xr3 = x + (size_t)(b0 + rg * 4 + 3) * Tt;
    const float* ptab = g_proj + (size_t)dir * Vv * G4;

    float c0 = 0.f, c1 = 0.f, c2 = 0.f, c3 = 0.f;

    // per-thread SMEM bases for the gate loop (buffer-relative offsets)
    const float* wb0 = W_s2 + (0 * 40 + j) * 2;
    const float* wb1 = W_s2 + (1 * 40 + j) * 2;
    const float* wb2 = W_s2 + (2 * 40 + j) * 2;
    const float* wb3 = W_s2 + (3 * 40 + j) * 2;
    const unsigned hb_off = (unsigned)(rg * 4) * 2;

    // staging word offset (within a buffer) for own h values
    const unsigned stage_base = ((unsigned)(h0 + j) >> 1) * 32 + ((unsigned)(h0 + j) & 1);
    // push mapping: own slice = contiguous words [h0*16, h0*16 + slice_words)
    const int slice_words = (rank == 7) ? 320 : 640;   // 20 or 40 valid cols
    const unsigned push_off = (unsigned)(h0 * 16) + (unsigned)tid * 4;
    const bool do_push = (tid * 4) < slice_words;

    // parity trackers for the two barriers
    uint32_t par0 = 0, par1 = 0;

    // ---- prologue: gather xp for step 0 ----
    float xp[16];
    {
        const int t0 = dir ? (Tt - 1) : 0;
        const float* p0 = ptab + (size_t)xr0[t0] * G4 + hjc;
        const float* p1 = ptab + (size_t)xr1[t0] * G4 + hjc;
        const float* p2 = ptab + (size_t)xr2[t0] * G4 + hjc;
        const float* p3 = ptab + (size_t)xr3[t0] * G4 + hjc;
#pragma unroll
        for (int g = 0; g < 4; g++) {
            xp[0 * 4 + g] = p0[g * Hh];
            xp[1 * 4 + g] = p1[g * Hh];
            xp[2 * 4 + g] = p2[g * Hh];
            xp[3 * 4 + g] = p3[g * Hh];
        }
    }

    for (int ti = 0; ti < Tt; ti++) {
        const int tcur = dir ? (Tt - 1 - ti) : ti;
        float* hcur  = (ti & 1) ? hbuf1 : hbuf0;
        float* hnext = (ti & 1) ? hbuf0 : hbuf1;

        // ---- prefetch next step's xp (starts before the wait; hidden) ----
        float xpn[16];
        {
            const int tin = (ti + 1 < Tt) ? (ti + 1) : ti;
            const int tn  = dir ? (Tt - 1 - tin) : tin;
            const float* p0 = ptab + (size_t)xr0[tn] * G4 + hjc;
            const float* p1 = ptab + (size_t)xr1[tn] * G4 + hjc;
            const float* p2 = ptab + (size_t)xr2[tn] * G4 + hjc;
            const float* p3 = ptab + (size_t)xr3[tn] * G4 + hjc;
#pragma unroll
            for (int g = 0; g < 4; g++) {
                xpn[0 * 4 + g] = p0[g * Hh];
                xpn[1 * 4 + g] = p1[g * Hh];
                xpn[2 * 4 + g] = p2[g * Hh];
                xpn[3 * 4 + g] = p3[g * Hh];
            }
        }

        // ---- wait for h of step ti-1 (all 8 CTAs' slices arrived) ----
        if (ti > 0) {
            if (ti & 1) { mbar_wait_parity_acq_cluster(mbar_addr1, par1); par1 ^= 1; }
            else        { mbar_wait_parity_acq_cluster(mbar_addr0, par0); par0 ^= 1; }
        }

        // ---- gate dots: acc2[r][g], f32x2 paired over (k even, k odd) ----
        const float* hb = hcur + hb_off;
        ull_t acc2[4][4];
#pragma unroll
        for (int r = 0; r < 4; r++)
#pragma unroll
            for (int g = 0; g < 4; g++) acc2[r][g] = 0ull;

#pragma unroll 5
        for (int k2 = 0; k2 < 150; k2++) {
            ull_t wv0 = *(const ull_t*)(wb0 + k2 * 320);
            ull_t wv1 = *(const ull_t*)(wb1 + k2 * 320);
            ull_t wv2 = *(const ull_t*)(wb2 + k2 * 320);
            ull_t wv3 = *(const ull_t*)(wb3 + k2 * 320);
            F4U h01, h23;
            h01.f = *(const float4*)(hb + k2 * 32);
            h23.f = *(const float4*)(hb + k2 * 32 + 4);
            ffma2(acc2[0][0], h01.u[0], wv0); ffma2(acc2[0][1], h01.u[0], wv1);
            ffma2(acc2[0][2], h01.u[0], wv2); ffma2(acc2[0][3], h01.u[0], wv3);
            ffma2(acc2[1][0], h01.u[1], wv0); ffma2(acc2[1][1], h01.u[1], wv1);
            ffma2(acc2[1][2], h01.u[1], wv2); ffma2(acc2[1][3], h01.u[1], wv3);
            ffma2(acc2[2][0], h23.u[0], wv0); ffma2(acc2[2][1], h23.u[0], wv1);
            ffma2(acc2[2][2], h23.u[0], wv2); ffma2(acc2[2][3], h23.u[0], wv3);
            ffma2(acc2[3][0], h23.u[1], wv0); ffma2(acc2[3][1], h23.u[1], wv1);
            ffma2(acc2[3][2], h23.u[1], wv2); ffma2(acc2[3][3], h23.u[1], wv3);
        }

        float acc[16];
#pragma unroll
        for (int r = 0; r < 4; r++)
#pragma unroll
            for (int g = 0; g < 4; g++) {
                U2F v; v.u = acc2[r][g];
                acc[r * 4 + g] = v.f.x + v.f.y;
            }

        // ---- LSTM cell update (c in registers) ----
        float hn[4];
        {
            float gi_, gf_, gg_, go_, tg;
            gi_ = acc[0] + xp[0];  gf_ = acc[1] + xp[1];  gg_ = acc[2] + xp[2];  go_ = acc[3] + xp[3];
            tg = tanhf_(gg_); c0 = sigmoidf_(gf_) * c0 + sigmoidf_(gi_) * tg; hn[0] = sigmoidf_(go_) * tanhf_(c0);
            gi_ = acc[4] + xp[4];  gf_ = acc[5] + xp[5];  gg_ = acc[6] + xp[6];  go_ = acc[7] + xp[7];
            tg = tanhf_(gg_); c1 = sigmoidf_(gf_) * c1 + sigmoidf_(gi_) * tg; hn[1] = sigmoidf_(go_) * tanhf_(c1);
            gi_ = acc[8] + xp[8];  gf_ = acc[9] + xp[9];  gg_ = acc[10] + xp[10]; go_ = acc[11] + xp[11];
            tg = tanhf_(gg_); c2 = sigmoidf_(gf_) * c2 + sigmoidf_(gi_) * tg; hn[2] = sigmoidf_(go_) * tanhf_(c2);
            gi_ = acc[12] + xp[12]; gf_ = acc[13] + xp[13]; gg_ = acc[14] + xp[14]; go_ = acc[15] + xp[15];
            tg = tanhf_(gg_); c3 = sigmoidf_(gf_) * c3 + sigmoidf_(gi_) * tg; hn[3] = sigmoidf_(go_) * tanhf_(c3);
        }

        if (ti + 1 < Tt) {
            // ---- stage new h into NEXT buffer's own slice (local) ----
            if (validh) {
                hnext[stage_base + (rg * 4 + 0) * 2] = hn[0];
                hnext[stage_base + (rg * 4 + 1) * 2] = hn[1];
                hnext[stage_base + (rg * 4 + 2) * 2] = hn[2];
                hnext[stage_base + (rg * 4 + 3) * 2] = hn[3];
            }
            __syncthreads();

            // ---- push own contiguous slice to 7 peers (fire-and-forget) ----
            if (do_push) {
                float4 v = *(const float4*)(hnext + push_off);
#pragma unroll
                for (int rr = 0; rr < 8; rr++) {
                    if (rr == rank) continue;
                    float* ph = cluster.map_shared_rank(hnext, rr);
                    *(float4*)(ph + push_off) = v;
                }
            }

            // ---- aggregated release-arrive on all 8 CTAs' barriers ----
            if (tid == 0) {
                asm volatile("fence.acq_rel.cluster;" ::: "memory");
                const uint32_t mb = (ti & 1) ? mbar_addr0 : mbar_addr1;  // barrier of NEXT buffer
#pragma unroll
                for (int rr = 0; rr < 8; rr++) mbar_arrive_rank(mb, rr);
            }
        }

        // ---- write h to global for the output stage (fills wait time) ----
        if (validh) {
            size_t base = ((size_t)(dir * Bb + b0 + rg * 4) * Tt + tcur) * Hh + (h0 + j);
            const size_t strideB = (size_t)Tt * Hh;
            g_h[base + 0 * strideB] = hn[0];
            g_h[base + 1 * strideB] = hn[1];
            g_h[base + 2 * strideB] = hn[2];
            g_h[base + 3 * strideB] = hn[3];
        }

        xp[0]=xpn[0]; xp[1]=xpn[1]; xp[2]=xpn[2]; xp[3]=xpn[3];
        xp[4]=xpn[4]; xp[5]=xpn[5]; xp[6]=xpn[6]; xp[7]=xpn[7];
        xp[8]=xpn[8]; xp[9]=xpn[9]; xp[10]=xpn[10]; xp[11]=xpn[11];
        xp[12]=xpn[12]; xp[13]=xpn[13]; xp[14]=xpn[14]; xp[15]=xpn[15];
    }
}

// =================================================================
// K3: output linear + softmax. One warp per (b,t).
// =================================================================
__global__ void out_kernel(const float* __restrict__ W_lin,
                           const float* __restrict__ b_lin,
                           float* __restrict__ out) {
    const int warp = (blockIdx.x * blockDim.x + threadIdx.x) >> 5;
    const int lane = threadIdx.x & 31;
    if (warp >= Bb * Tt) return;
    const int b = warp / Tt;
    const int t = warp % Tt;

    const float* hf = g_h + ((size_t)(0 * Bb + b) * Tt + t) * Hh;
    const float* hb = g_h + ((size_t)(1 * Bb + b) * Tt + t) * Hh;

    float acc[Oo];
#pragma unroll
    for (int o = 0; o < Oo; o++) acc[o] = 0.f;

    for (int k = lane; k < Hh; k += 32) {
        float a = hf[k];
        float c = hb[k];
#pragma unroll
        for (int o = 0; o < Oo; o++)
            acc[o] += a * W_lin[o * (2 * Hh) + k] + c * W_lin[o * (2 * Hh) + Hh + k];
    }
#pragma unroll
    for (int o = 0; o < Oo; o++) {
#pragma unroll
        for (int off = 16; off > 0; off >>= 1)
            acc[o] += __shfl_xor_sync(0xFFFFFFFFu, acc[o], off);
        acc[o] += b_lin[o];
    }
    float mx = acc[0];
#pragma unroll
    for (int o = 1; o < Oo; o++) mx = fmaxf(mx, acc[o]);
    float s = 0.f;
    float e[Oo];
#pragma unroll
    for (int o = 0; o < Oo; o++) { e[o] = __expf(acc[o] - mx); s += e[o]; }
    float inv = 1.0f / s;
    if (lane < Oo) out[(size_t)warp * Oo + lane] = e[lane] * inv;
}

// =================================================================
// launcher
// =================================================================
extern "C" void kernel_launch(void* const* d_in, const int* in_sizes, int n_in,
                              void* d_out, int out_size) {
    const int*   x     = (const int*)  d_in[0];
    const float* emb   = (const float*)d_in[1];
    const float* Wih_f = (const float*)d_in[2];
    const float* Whh_f = (const float*)d_in[3];
    const float* b_f   = (const float*)d_in[4];
    const float* Wih_b = (const float*)d_in[5];
    const float* Whh_b = (const float*)d_in[6];
    const float* b_b   = (const float*)d_in[7];
    const float* W_lin = (const float*)d_in[8];
    const float* b_lin = (const float*)d_in[9];
    float* out = (float*)d_out;

    cudaFuncSetAttribute(lstm_rec_kernel,
                         cudaFuncAttributeMaxDynamicSharedMemorySize, REC_SMEM);

    // K1: vocab projection. grid = (N tiles, M tiles, dir)
    {
        dim3 grid((G4 + K1_BN - 1) / K1_BN, Vv / K1_BM, 2);
        proj_kernel<<<grid, 256>>>(emb, Wih_f, Wih_b, b_f, b_b);
    }
    // K2: recurrence. 128 CTAs, clusters of 8.
    lstm_rec_kernel<<<128, REC_THREADS, REC_SMEM>>>(x, Whh_f, Whh_b);

    // K3: output. 65536 warps.
    {
        int warps_per_block = 8;
        int blocks = (Bb * Tt) / warps_per_block;
        out_kernel<<<blocks, warps_per_block * 32>>>(W_lin, b_lin, out);
    }
}